// round 1
// baseline (speedup 1.0000x reference)
#include <cuda_runtime.h>

// ---------------- problem constants ----------------
#define BATCH    2
#define S_LEN    2048
#define D_DIM    1024
#define N_HEADS  16
#define HEAD_DIM 64
#define M_ROWS   (BATCH * S_LEN)   // 4096

// ---------------- device scratch (no cudaMalloc allowed) ----------------
__device__ float g_q[BATCH * N_HEADS * S_LEN * HEAD_DIM];   // [B,H,S,HD]
__device__ float g_k[BATCH * N_HEADS * S_LEN * HEAD_DIM];
__device__ float g_v[BATCH * N_HEADS * S_LEN * HEAD_DIM];
__device__ float g_ctx[M_ROWS * D_DIM];                     // [B,S,D]
__device__ float g_x[M_ROWS * D_DIM];                       // proj + residual

// =====================================================================
// SGEMM: C = A[M,K] * B[K,N] (+bias) with fused epilogue
//   MODE 0: scatter into [B,H,S,HD] layout (QKV projections), +bias
//   MODE 1: +bias +residual, row-major [M,N] output (O projection)
// 128x128 tile, BK=8, 256 threads, 8x8 per thread.
// =====================================================================
#define GBM 128
#define GBN 128
#define GBK 8
#define GTM 8
#define GTN 8

template <int MODE>
__global__ __launch_bounds__(256) void sgemm_k(
    const float* __restrict__ A, const float* __restrict__ B,
    const float* __restrict__ bias, const float* __restrict__ resid,
    float* __restrict__ C)
{
    const int M = M_ROWS, N = D_DIM, K = D_DIM;
    __shared__ float As[GBK][GBM];
    __shared__ float Bs[GBK][GBN];

    const int bx = blockIdx.x, by = blockIdx.y;
    const int tid = threadIdx.x;
    const int tr = tid / (GBN / GTN);   // 0..15
    const int tc = tid % (GBN / GTN);   // 0..15

    const float* Ab = A + (size_t)by * GBM * K;
    const float* Bb = B + (size_t)bx * GBN;

    const int arow = tid / (GBK / 4);          // 0..127
    const int acol = (tid % (GBK / 4)) * 4;    // 0 or 4
    const int brow = tid / (GBN / 4);          // 0..7
    const int bcol = (tid % (GBN / 4)) * 4;    // 0..124

    float acc[GTM][GTN];
#pragma unroll
    for (int i = 0; i < GTM; i++)
#pragma unroll
        for (int j = 0; j < GTN; j++) acc[i][j] = 0.f;

    float regM[GTM], regN[GTN];

    for (int k0 = 0; k0 < K; k0 += GBK) {
        float4 a4 = *(const float4*)(Ab + (size_t)arow * K + k0 + acol);
        As[acol + 0][arow] = a4.x;
        As[acol + 1][arow] = a4.y;
        As[acol + 2][arow] = a4.z;
        As[acol + 3][arow] = a4.w;
        float4 b4 = *(const float4*)(Bb + (size_t)(k0 + brow) * N + bcol);
        *(float4*)&Bs[brow][bcol] = b4;
        __syncthreads();

#pragma unroll
        for (int kk = 0; kk < GBK; kk++) {
#pragma unroll
            for (int i = 0; i < GTM; i += 4)
                *(float4*)&regM[i] = *(const float4*)&As[kk][tr * GTM + i];
#pragma unroll
            for (int j = 0; j < GTN; j += 4)
                *(float4*)&regN[j] = *(const float4*)&Bs[kk][tc * GTN + j];
#pragma unroll
            for (int i = 0; i < GTM; i++)
#pragma unroll
                for (int j = 0; j < GTN; j++)
                    acc[i][j] += regM[i] * regN[j];
        }
        __syncthreads();
    }

    // epilogue
#pragma unroll
    for (int i = 0; i < GTM; i++) {
        const int m = by * GBM + tr * GTM + i;
        const int bb = m >> 11;        // / S_LEN
        const int srow = m & (S_LEN - 1);
#pragma unroll
        for (int j = 0; j < GTN; j += 4) {
            const int n = bx * GBN + tc * GTN + j;
            float4 r;
            r.x = acc[i][j + 0] + bias[n + 0];
            r.y = acc[i][j + 1] + bias[n + 1];
            r.z = acc[i][j + 2] + bias[n + 2];
            r.w = acc[i][j + 3] + bias[n + 3];
            if (MODE == 0) {
                const int hh = n >> 6, dd = n & 63;
                size_t idx = (((size_t)bb * N_HEADS + hh) * S_LEN + srow) * HEAD_DIM + dd;
                *(float4*)(C + idx) = r;
            } else {
                size_t idx = (size_t)m * N + n;
                float4 rr = *(const float4*)(resid + idx);
                r.x += rr.x; r.y += rr.y; r.z += rr.z; r.w += rr.w;
                *(float4*)(C + idx) = r;
            }
        }
    }
}

// =====================================================================
// Flash attention: one CTA = 64 Q rows of one (b,h); loops 64-key tiles.
// smem layouts (pad 65 to avoid stride-64 bank conflicts):
//   Qs[d*65 + r], Ks[d*65 + c], Ps[c*65 + r], Vs[c*64 + d]
// =====================================================================
#define FL_SMEM ((3 * 64 * 65 + 64 * 64) * 4)   // 66304 bytes

__global__ __launch_bounds__(256) void flash_attn(
    const float* __restrict__ Q, const float* __restrict__ K,
    const float* __restrict__ V, const float* __restrict__ mask,
    float* __restrict__ O)
{
    extern __shared__ float sm[];
    float* Qs = sm;                // 64*65
    float* Ks = Qs + 64 * 65;      // 64*65
    float* Ps = Ks + 64 * 65;      // 64*65
    float* Vs = Ps + 64 * 65;      // 64*64

    const int bh = blockIdx.y;
    const int b  = bh >> 4;
    const int h  = bh & 15;
    const int qb = blockIdx.x;
    const int tid = threadIdx.x;
    const int tx = tid & 15;
    const int ty = tid >> 4;
    const int r0 = ty * 4, c0 = tx * 4;

    const float* Qp = Q + ((size_t)bh * S_LEN + qb * 64) * HEAD_DIM;
    const float* Kp = K + (size_t)bh * S_LEN * HEAD_DIM;
    const float* Vp = V + (size_t)bh * S_LEN * HEAD_DIM;
    const float* mp = mask + (size_t)b * S_LEN;

    // load Q transposed, fold 1/sqrt(HD)=0.125 into Q
    for (int i = tid; i < 64 * 64; i += 256) {
        const int r = i >> 6, d = i & 63;
        Qs[d * 65 + r] = Qp[i] * 0.125f;
    }

    float m_i[4], l_i[4], o[4][4];
#pragma unroll
    for (int i = 0; i < 4; i++) {
        m_i[i] = -1e30f; l_i[i] = 0.f;
#pragma unroll
        for (int j = 0; j < 4; j++) o[i][j] = 0.f;
    }

    for (int kb = 0; kb < S_LEN / 64; kb++) {
        __syncthreads();   // prev-iter consumers of Ks/Vs/Ps are done
        const float* kp = Kp + (size_t)kb * 64 * HEAD_DIM;
        const float* vp = Vp + (size_t)kb * 64 * HEAD_DIM;
        for (int i = tid; i < 64 * 64; i += 256) {
            const int r = i >> 6, d = i & 63;
            Ks[d * 65 + r] = kp[i];
        }
        for (int i = tid * 4; i < 64 * 64; i += 1024)
            *(float4*)(Vs + i) = *(const float4*)(vp + i);
        __syncthreads();

        // S = Q * K^T  (64x64x64)
        float s[4][4];
#pragma unroll
        for (int i = 0; i < 4; i++)
#pragma unroll
            for (int j = 0; j < 4; j++) s[i][j] = 0.f;

#pragma unroll 16
        for (int d = 0; d < 64; d++) {
            const float q0 = Qs[d * 65 + r0 + 0];
            const float q1 = Qs[d * 65 + r0 + 1];
            const float q2 = Qs[d * 65 + r0 + 2];
            const float q3 = Qs[d * 65 + r0 + 3];
            const float k0 = Ks[d * 65 + c0 + 0];
            const float k1 = Ks[d * 65 + c0 + 1];
            const float k2 = Ks[d * 65 + c0 + 2];
            const float k3 = Ks[d * 65 + c0 + 3];
            s[0][0] += q0 * k0; s[0][1] += q0 * k1; s[0][2] += q0 * k2; s[0][3] += q0 * k3;
            s[1][0] += q1 * k0; s[1][1] += q1 * k1; s[1][2] += q1 * k2; s[1][3] += q1 * k3;
            s[2][0] += q2 * k0; s[2][1] += q2 * k1; s[2][2] += q2 * k2; s[2][3] += q2 * k3;
            s[3][0] += q3 * k0; s[3][1] += q3 * k1; s[3][2] += q3 * k2; s[3][3] += q3 * k3;
        }

        // additive attention mask (per key column)
        const float mk0 = mp[kb * 64 + c0 + 0];
        const float mk1 = mp[kb * 64 + c0 + 1];
        const float mk2 = mp[kb * 64 + c0 + 2];
        const float mk3 = mp[kb * 64 + c0 + 3];
#pragma unroll
        for (int i = 0; i < 4; i++) {
            s[i][0] += mk0; s[i][1] += mk1; s[i][2] += mk2; s[i][3] += mk3;
        }

        // online softmax (row groups of 16 lanes share a q-row set)
#pragma unroll
        for (int i = 0; i < 4; i++) {
            float mx = fmaxf(fmaxf(s[i][0], s[i][1]), fmaxf(s[i][2], s[i][3]));
#pragma unroll
            for (int off = 8; off; off >>= 1)
                mx = fmaxf(mx, __shfl_xor_sync(0xffffffffu, mx, off, 16));
            const float mn = fmaxf(m_i[i], mx);
            const float al = __expf(m_i[i] - mn);
            m_i[i] = mn;
            float rs = 0.f;
#pragma unroll
            for (int j = 0; j < 4; j++) {
                s[i][j] = __expf(s[i][j] - mn);
                rs += s[i][j];
            }
#pragma unroll
            for (int off = 8; off; off >>= 1)
                rs += __shfl_xor_sync(0xffffffffu, rs, off, 16);
            l_i[i] = l_i[i] * al + rs;
#pragma unroll
            for (int j = 0; j < 4; j++) {
                o[i][j] *= al;
                Ps[(c0 + j) * 65 + r0 + i] = s[i][j];
            }
        }
        __syncthreads();

        // O += P * V  (64x64x64)
#pragma unroll 8
        for (int c = 0; c < 64; c++) {
            const float4 vv = *(const float4*)(Vs + c * 64 + c0);
            const float p0 = Ps[c * 65 + r0 + 0];
            const float p1 = Ps[c * 65 + r0 + 1];
            const float p2 = Ps[c * 65 + r0 + 2];
            const float p3 = Ps[c * 65 + r0 + 3];
            o[0][0] += p0 * vv.x; o[0][1] += p0 * vv.y; o[0][2] += p0 * vv.z; o[0][3] += p0 * vv.w;
            o[1][0] += p1 * vv.x; o[1][1] += p1 * vv.y; o[1][2] += p1 * vv.z; o[1][3] += p1 * vv.w;
            o[2][0] += p2 * vv.x; o[2][1] += p2 * vv.y; o[2][2] += p2 * vv.z; o[2][3] += p2 * vv.w;
            o[3][0] += p3 * vv.x; o[3][1] += p3 * vv.y; o[3][2] += p3 * vv.z; o[3][3] += p3 * vv.w;
        }
    }

    // write ctx in [B,S,D] layout directly (D col = h*64 + d)
#pragma unroll
    for (int i = 0; i < 4; i++) {
        const float inv = 1.f / l_i[i];
        const int srow = qb * 64 + r0 + i;
        float4 ov = make_float4(o[i][0] * inv, o[i][1] * inv, o[i][2] * inv, o[i][3] * inv);
        *(float4*)(O + ((size_t)b * S_LEN + srow) * D_DIM + h * HEAD_DIM + c0) = ov;
    }
}

// =====================================================================
// LayerNorm over last dim (1024), one CTA (256 thr) per row
// =====================================================================
__global__ __launch_bounds__(256) void layernorm_k(
    const float* __restrict__ X, const float* __restrict__ gamma,
    const float* __restrict__ beta, float* __restrict__ out)
{
    __shared__ float red[16];
    const int row = blockIdx.x;
    const int tid = threadIdx.x;
    const float* x = X + (size_t)row * D_DIM;

    float4 v = *(const float4*)(x + tid * 4);
    float s  = v.x + v.y + v.z + v.w;
    float sq = v.x * v.x + v.y * v.y + v.z * v.z + v.w * v.w;
#pragma unroll
    for (int off = 16; off; off >>= 1) {
        s  += __shfl_xor_sync(0xffffffffu, s, off);
        sq += __shfl_xor_sync(0xffffffffu, sq, off);
    }
    const int wid = tid >> 5;
    if ((tid & 31) == 0) { red[wid] = s; red[8 + wid] = sq; }
    __syncthreads();
    if (tid < 32) {
        float ss = (tid < 8) ? red[tid] : 0.f;
        float qq = (tid < 8) ? red[8 + tid] : 0.f;
#pragma unroll
        for (int off = 4; off; off >>= 1) {
            ss += __shfl_xor_sync(0xffffffffu, ss, off);
            qq += __shfl_xor_sync(0xffffffffu, qq, off);
        }
        if (tid == 0) { red[0] = ss; red[1] = qq; }
    }
    __syncthreads();
    const float mu   = red[0] * (1.f / D_DIM);
    const float var  = red[1] * (1.f / D_DIM) - mu * mu;
    const float rstd = rsqrtf(var + 1e-12f);

    float4 g4 = *(const float4*)(gamma + tid * 4);
    float4 b4 = *(const float4*)(beta + tid * 4);
    float4 r;
    r.x = (v.x - mu) * rstd * g4.x + b4.x;
    r.y = (v.y - mu) * rstd * g4.y + b4.y;
    r.z = (v.z - mu) * rstd * g4.z + b4.z;
    r.w = (v.w - mu) * rstd * g4.w + b4.w;
    *(float4*)(out + (size_t)row * D_DIM + tid * 4) = r;
}

// =====================================================================
// launch
// =====================================================================
extern "C" void kernel_launch(void* const* d_in, const int* in_sizes, int n_in,
                              void* d_out, int out_size)
{
    const float* hs   = (const float*)d_in[0];
    const float* mask = (const float*)d_in[1];
    const float* Wq   = (const float*)d_in[2];
    const float* bq   = (const float*)d_in[3];
    const float* Wk   = (const float*)d_in[4];
    const float* bk   = (const float*)d_in[5];
    const float* Wv   = (const float*)d_in[6];
    const float* bv   = (const float*)d_in[7];
    const float* Wo   = (const float*)d_in[8];
    const float* bo   = (const float*)d_in[9];
    const float* gm   = (const float*)d_in[10];
    const float* bt   = (const float*)d_in[11];
    float* out = (float*)d_out;

    float *qp, *kp, *vp, *cp, *xp;
    cudaGetSymbolAddress((void**)&qp, g_q);
    cudaGetSymbolAddress((void**)&kp, g_k);
    cudaGetSymbolAddress((void**)&vp, g_v);
    cudaGetSymbolAddress((void**)&cp, g_ctx);
    cudaGetSymbolAddress((void**)&xp, g_x);

    const dim3 gg(D_DIM / GBN, M_ROWS / GBM);   // (8, 32)

    sgemm_k<0><<<gg, 256>>>(hs, Wq, bq, nullptr, qp);
    sgemm_k<0><<<gg, 256>>>(hs, Wk, bk, nullptr, kp);
    sgemm_k<0><<<gg, 256>>>(hs, Wv, bv, nullptr, vp);

    cudaFuncSetAttribute(flash_attn, cudaFuncAttributeMaxDynamicSharedMemorySize, FL_SMEM);
    flash_attn<<<dim3(S_LEN / 64, BATCH * N_HEADS), 256, FL_SMEM>>>(qp, kp, vp, mask, cp);

    sgemm_k<1><<<gg, 256>>>(cp, Wo, bo, hs, xp);

    layernorm_k<<<M_ROWS, 256>>>(xp, gm, bt, out);
}

// round 2
// speedup vs baseline: 2.3816x; 2.3816x over previous
#include <cuda_runtime.h>
#include <cstdint>

// ---------------- problem constants ----------------
#define BATCH    2
#define S_LEN    2048
#define D_DIM    1024
#define N_HEADS  16
#define HEAD_DIM 64
#define M_ROWS   (BATCH * S_LEN)   // 4096

// ---------------- device scratch ----------------
__device__ float g_q[BATCH * N_HEADS * S_LEN * HEAD_DIM];   // [B,H,S,HD]
__device__ float g_k[BATCH * N_HEADS * S_LEN * HEAD_DIM];
__device__ float g_v[BATCH * N_HEADS * S_LEN * HEAD_DIM];
__device__ float g_ctx[M_ROWS * D_DIM];                     // [B,S,D]
__device__ float g_x[M_ROWS * D_DIM];                       // proj + residual

// ---------------- ptx helpers ----------------
__device__ __forceinline__ void cp_a16(void* s, const void* g) {
    uint32_t sa = (uint32_t)__cvta_generic_to_shared(s);
    asm volatile("cp.async.cg.shared.global [%0], [%1], 16;\n" :: "r"(sa), "l"(g));
}
__device__ __forceinline__ void cp_commit() {
    asm volatile("cp.async.commit_group;\n" ::: "memory");
}
template <int N> __device__ __forceinline__ void cp_wait() {
    asm volatile("cp.async.wait_group %0;\n" :: "n"(N) : "memory");
}
// D(16x8) += A(16x8,row) * B(8x8,col), tf32 inputs (raw fp32 bits -> HW truncation)
__device__ __forceinline__ void mma8(float* c, const uint32_t* a, const uint32_t* b) {
    asm volatile(
        "mma.sync.aligned.m16n8k8.row.col.f32.tf32.tf32.f32 "
        "{%0,%1,%2,%3}, {%4,%5,%6,%7}, {%8,%9}, {%0,%1,%2,%3};\n"
        : "+f"(c[0]), "+f"(c[1]), "+f"(c[2]), "+f"(c[3])
        : "r"(a[0]), "r"(a[1]), "r"(a[2]), "r"(a[3]), "r"(b[0]), "r"(b[1]));
}

// =====================================================================
// TF32 GEMM: C = A[M,K] * W[K,N] (+bias [+resid])
//   MODE 0: scatter into [B,H,S,HD] (QKV; blockIdx.z selects W/bias/out)
//   MODE 1: +bias +resid, row-major out
// 128x128x32 tile, 256 thr (8 warps, 2x4), warp tile 64x32, m16n8k8.
// =====================================================================
#define ASTR 36
#define BSTR 132
#define A_ELE (128 * ASTR)
#define B_ELE (32 * BSTR)
#define STAGE (A_ELE + B_ELE)
#define GEMM_SMEM (2 * STAGE * 4)

template <int MODE>
__global__ __launch_bounds__(256) void gemm_tf32(
    const float* __restrict__ A,
    const float* __restrict__ W0, const float* __restrict__ W1, const float* __restrict__ W2,
    const float* __restrict__ bp0, const float* __restrict__ bp1, const float* __restrict__ bp2,
    const float* __restrict__ resid,
    float* __restrict__ C0, float* __restrict__ C1, float* __restrict__ C2)
{
    extern __shared__ float sm[];
    const int K = D_DIM, N = D_DIM;
    const int z = blockIdx.z;
    const float* W    = (z == 0) ? W0  : (z == 1) ? W1  : W2;
    const float* bias = (z == 0) ? bp0 : (z == 1) ? bp1 : bp2;
    float*       C    = (z == 0) ? C0  : (z == 1) ? C1  : C2;

    const int tid  = threadIdx.x;
    const int lane = tid & 31;
    const int g    = lane >> 2, tig = lane & 3;
    const int wid  = tid >> 5;
    const int wm   = wid >> 2, wn = wid & 3;          // 2x4 warp grid
    const int bm   = blockIdx.y * 128, bn = blockIdx.x * 128;

    const int arow = tid >> 1, acb = (tid & 1) * 16;
    const int brow = tid >> 3, bcb = (tid & 7) * 16;

    float acc[4][4][4];
#pragma unroll
    for (int i = 0; i < 4; i++)
#pragma unroll
        for (int j = 0; j < 4; j++)
#pragma unroll
            for (int r = 0; r < 4; r++) acc[i][j][r] = 0.f;

    // prefetch stage 0
    {
        float* As = sm;
        float* Bs = sm + A_ELE;
#pragma unroll
        for (int i = 0; i < 4; i++)
            cp_a16(&As[arow * ASTR + acb + 4 * i], &A[(size_t)(bm + arow) * K + acb + 4 * i]);
#pragma unroll
        for (int i = 0; i < 4; i++)
            cp_a16(&Bs[brow * BSTR + bcb + 4 * i], &W[(size_t)brow * N + bn + bcb + 4 * i]);
        cp_commit();
    }

    const int KT = K / 32;
    for (int kt = 0; kt < KT; kt++) {
        if (kt + 1 < KT) {
            float* As = sm + ((kt + 1) & 1) * STAGE;
            float* Bs = As + A_ELE;
            const int k0 = (kt + 1) * 32;
#pragma unroll
            for (int i = 0; i < 4; i++)
                cp_a16(&As[arow * ASTR + acb + 4 * i], &A[(size_t)(bm + arow) * K + k0 + acb + 4 * i]);
#pragma unroll
            for (int i = 0; i < 4; i++)
                cp_a16(&Bs[brow * BSTR + bcb + 4 * i], &W[(size_t)(k0 + brow) * N + bn + bcb + 4 * i]);
            cp_commit();
            cp_wait<1>();
        } else {
            cp_wait<0>();
        }
        __syncthreads();

        const float* As = sm + (kt & 1) * STAGE;
        const float* Bs = As + A_ELE;
#pragma unroll
        for (int kk = 0; kk < 32; kk += 8) {
            uint32_t af[4][4], bf[4][2];
#pragma unroll
            for (int mt = 0; mt < 4; mt++) {
                const int r0 = wm * 64 + mt * 16;
                af[mt][0] = __float_as_uint(As[(r0 + g) * ASTR + kk + tig]);
                af[mt][1] = __float_as_uint(As[(r0 + g + 8) * ASTR + kk + tig]);
                af[mt][2] = __float_as_uint(As[(r0 + g) * ASTR + kk + tig + 4]);
                af[mt][3] = __float_as_uint(As[(r0 + g + 8) * ASTR + kk + tig + 4]);
            }
#pragma unroll
            for (int nt = 0; nt < 4; nt++) {
                const int c0 = wn * 32 + nt * 8;
                bf[nt][0] = __float_as_uint(Bs[(kk + tig) * BSTR + c0 + g]);
                bf[nt][1] = __float_as_uint(Bs[(kk + tig + 4) * BSTR + c0 + g]);
            }
#pragma unroll
            for (int mt = 0; mt < 4; mt++)
#pragma unroll
                for (int nt = 0; nt < 4; nt++)
                    mma8(acc[mt][nt], af[mt], bf[nt]);
        }
        __syncthreads();
    }

    // epilogue
#pragma unroll
    for (int mt = 0; mt < 4; mt++) {
#pragma unroll
        for (int nt = 0; nt < 4; nt++) {
            const int n  = bn + wn * 32 + nt * 8 + 2 * tig;
            const float bx = bias[n], by = bias[n + 1];
#pragma unroll
            for (int half = 0; half < 2; half++) {
                const int m = bm + wm * 64 + mt * 16 + g + half * 8;
                float2 r;
                r.x = acc[mt][nt][half * 2 + 0] + bx;
                r.y = acc[mt][nt][half * 2 + 1] + by;
                if (MODE == 0) {
                    const int bb = m >> 11, srow = m & (S_LEN - 1);
                    const int hh = n >> 6, dd = n & 63;
                    size_t idx = (((size_t)bb * N_HEADS + hh) * S_LEN + srow) * HEAD_DIM + dd;
                    *(float2*)(C + idx) = r;
                } else {
                    size_t idx = (size_t)m * N + n;
                    float2 rr = *(const float2*)(resid + idx);
                    r.x += rr.x; r.y += rr.y;
                    *(float2*)(C + idx) = r;
                }
            }
        }
    }
}

// =====================================================================
// TF32 flash attention: CTA = 64 Q rows of one (b,h), 4 warps (16 rows ea),
// 64-key tiles, cp.async double-buffered K/V, online softmax on fragments.
// =====================================================================
#define KST 68
#define KV_ELE (64 * KST)                      // one K or V stage
#define FL_SMEM ((4 * KV_ELE + KV_ELE) * 4)    // K0,K1,V0,V1,Ps = 87040 B

__global__ __launch_bounds__(128) void flash_tf32(
    const float* __restrict__ Q, const float* __restrict__ K,
    const float* __restrict__ V, const float* __restrict__ mask,
    float* __restrict__ O)
{
    extern __shared__ float sm[];
    float* Kbuf[2] = { sm, sm + KV_ELE };
    float* Vbuf[2] = { sm + 2 * KV_ELE, sm + 3 * KV_ELE };
    float* Ps      = sm + 4 * KV_ELE;

    const int bh = blockIdx.y;
    const int b  = bh >> 4, h = bh & 15;
    const int qb = blockIdx.x;
    const int tid  = threadIdx.x;
    const int wid  = tid >> 5, lane = tid & 31;
    const int g    = lane >> 2, tig = lane & 3;
    const int r0   = wid * 16;

    const float* Qp = Q + ((size_t)bh * S_LEN + qb * 64) * HEAD_DIM;
    const float* Kp = K + (size_t)bh * S_LEN * HEAD_DIM;
    const float* Vp = V + (size_t)bh * S_LEN * HEAD_DIM;
    const float* mp = mask + (size_t)b * S_LEN;

    // ---- stage Q through Ps (scaled by 1/8), prefetch tile 0 in parallel ----
    {
        float* Ks0 = Kbuf[0];
        float* Vs0 = Vbuf[0];
#pragma unroll
        for (int i = 0; i < 8; i++) {
            const int idx = i * 128 + tid;          // 1024 float4 per tile
            const int r = idx >> 4, c4 = (idx & 15) * 4;
            cp_a16(&Ks0[r * KST + c4], &Kp[r * 64 + c4]);
        }
#pragma unroll
        for (int i = 0; i < 8; i++) {
            const int idx = i * 128 + tid;
            const int r = idx >> 4, c4 = (idx & 15) * 4;
            cp_a16(&Vs0[r * KST + c4], &Vp[r * 64 + c4]);
        }
        cp_commit();
    }
#pragma unroll
    for (int i = 0; i < 8; i++) {
        const int idx = i * 128 + tid;
        const int r = idx >> 4, c4 = (idx & 15) * 4;
        float4 qv = *(const float4*)(Qp + r * 64 + c4);
        qv.x *= 0.125f; qv.y *= 0.125f; qv.z *= 0.125f; qv.w *= 0.125f;
        *(float4*)(Ps + r * KST + c4) = qv;
    }
    __syncthreads();

    // ---- extract per-warp Q fragments (registers, persistent) ----
    uint32_t qf[8][4];
#pragma unroll
    for (int kt = 0; kt < 8; kt++) {
        const int kk = kt * 8;
        qf[kt][0] = __float_as_uint(Ps[(r0 + g) * KST + kk + tig]);
        qf[kt][1] = __float_as_uint(Ps[(r0 + g + 8) * KST + kk + tig]);
        qf[kt][2] = __float_as_uint(Ps[(r0 + g) * KST + kk + tig + 4]);
        qf[kt][3] = __float_as_uint(Ps[(r0 + g + 8) * KST + kk + tig + 4]);
    }
    __syncthreads();   // everyone done with Q staging before Ps is reused for P

    float m0 = -1e30f, m1 = -1e30f, l0 = 0.f, l1 = 0.f;
    float o[8][4];
#pragma unroll
    for (int nt = 0; nt < 8; nt++)
#pragma unroll
        for (int r = 0; r < 4; r++) o[nt][r] = 0.f;

    const int NTILE = S_LEN / 64;   // 32
    for (int kb = 0; kb < NTILE; kb++) {
        if (kb + 1 < NTILE) {
            float* Ksn = Kbuf[(kb + 1) & 1];
            float* Vsn = Vbuf[(kb + 1) & 1];
            const float* kp = Kp + (size_t)(kb + 1) * 64 * HEAD_DIM;
            const float* vp = Vp + (size_t)(kb + 1) * 64 * HEAD_DIM;
#pragma unroll
            for (int i = 0; i < 8; i++) {
                const int idx = i * 128 + tid;
                const int r = idx >> 4, c4 = (idx & 15) * 4;
                cp_a16(&Ksn[r * KST + c4], &kp[r * 64 + c4]);
            }
#pragma unroll
            for (int i = 0; i < 8; i++) {
                const int idx = i * 128 + tid;
                const int r = idx >> 4, c4 = (idx & 15) * 4;
                cp_a16(&Vsn[r * KST + c4], &vp[r * 64 + c4]);
            }
            cp_commit();
            cp_wait<1>();
        } else {
            cp_wait<0>();
        }
        __syncthreads();

        const float* Ks = Kbuf[kb & 1];
        const float* Vs = Vbuf[kb & 1];

        // ---- S = Q * K^T (warp: 16 x 64) ----
        float s[8][4];
#pragma unroll
        for (int nt = 0; nt < 8; nt++)
#pragma unroll
            for (int r = 0; r < 4; r++) s[nt][r] = 0.f;

#pragma unroll
        for (int kt = 0; kt < 8; kt++) {
            const int kk = kt * 8;
#pragma unroll
            for (int nt = 0; nt < 8; nt++) {
                uint32_t bf[2];
                bf[0] = __float_as_uint(Ks[(nt * 8 + g) * KST + kk + tig]);
                bf[1] = __float_as_uint(Ks[(nt * 8 + g) * KST + kk + tig + 4]);
                mma8(s[nt], qf[kt], bf);
            }
        }

        // ---- mask + online softmax ----
        const float* mkp = mp + kb * 64;
        float mx0 = -1e30f, mx1 = -1e30f;
#pragma unroll
        for (int nt = 0; nt < 8; nt++) {
            const float ma = mkp[nt * 8 + 2 * tig];
            const float mb = mkp[nt * 8 + 2 * tig + 1];
            s[nt][0] += ma; s[nt][1] += mb; s[nt][2] += ma; s[nt][3] += mb;
            mx0 = fmaxf(mx0, fmaxf(s[nt][0], s[nt][1]));
            mx1 = fmaxf(mx1, fmaxf(s[nt][2], s[nt][3]));
        }
#pragma unroll
        for (int off = 1; off <= 2; off <<= 1) {
            mx0 = fmaxf(mx0, __shfl_xor_sync(0xffffffffu, mx0, off));
            mx1 = fmaxf(mx1, __shfl_xor_sync(0xffffffffu, mx1, off));
        }
        const float mn0 = fmaxf(m0, mx0), mn1 = fmaxf(m1, mx1);
        const float al0 = __expf(m0 - mn0), al1 = __expf(m1 - mn1);
        m0 = mn0; m1 = mn1;

        float rs0 = 0.f, rs1 = 0.f;
#pragma unroll
        for (int nt = 0; nt < 8; nt++) {
            s[nt][0] = __expf(s[nt][0] - mn0);
            s[nt][1] = __expf(s[nt][1] - mn0);
            s[nt][2] = __expf(s[nt][2] - mn1);
            s[nt][3] = __expf(s[nt][3] - mn1);
            rs0 += s[nt][0] + s[nt][1];
            rs1 += s[nt][2] + s[nt][3];
        }
#pragma unroll
        for (int off = 1; off <= 2; off <<= 1) {
            rs0 += __shfl_xor_sync(0xffffffffu, rs0, off);
            rs1 += __shfl_xor_sync(0xffffffffu, rs1, off);
        }
        l0 = l0 * al0 + rs0;
        l1 = l1 * al1 + rs1;

#pragma unroll
        for (int nt = 0; nt < 8; nt++) {
            o[nt][0] *= al0; o[nt][1] *= al0;
            o[nt][2] *= al1; o[nt][3] *= al1;
            // stash P in warp-private smem rows
            *(float2*)&Ps[(r0 + g) * KST + nt * 8 + 2 * tig]     = make_float2(s[nt][0], s[nt][1]);
            *(float2*)&Ps[(r0 + g + 8) * KST + nt * 8 + 2 * tig] = make_float2(s[nt][2], s[nt][3]);
        }
        __syncwarp();

        // ---- O += P * V (warp: 16 x 64 over 64 keys) ----
#pragma unroll
        for (int kt = 0; kt < 8; kt++) {
            const int ks = kt * 8;
            uint32_t af[4];
            af[0] = __float_as_uint(Ps[(r0 + g) * KST + ks + tig]);
            af[1] = __float_as_uint(Ps[(r0 + g + 8) * KST + ks + tig]);
            af[2] = __float_as_uint(Ps[(r0 + g) * KST + ks + tig + 4]);
            af[3] = __float_as_uint(Ps[(r0 + g + 8) * KST + ks + tig + 4]);
#pragma unroll
            for (int nt = 0; nt < 8; nt++) {
                uint32_t bf[2];
                bf[0] = __float_as_uint(Vs[(ks + tig) * KST + nt * 8 + g]);
                bf[1] = __float_as_uint(Vs[(ks + tig + 4) * KST + nt * 8 + g]);
                mma8(o[nt], af, bf);
            }
        }
        __syncthreads();   // protect K/V buffer being refilled next iter
    }

    // ---- write ctx [B,S,D] ----
    const float inv0 = 1.f / l0, inv1 = 1.f / l1;
#pragma unroll
    for (int nt = 0; nt < 8; nt++) {
        const int col = h * HEAD_DIM + nt * 8 + 2 * tig;
        const int row = qb * 64 + r0 + g;
        *(float2*)(O + ((size_t)b * S_LEN + row) * D_DIM + col) =
            make_float2(o[nt][0] * inv0, o[nt][1] * inv0);
        *(float2*)(O + ((size_t)b * S_LEN + row + 8) * D_DIM + col) =
            make_float2(o[nt][2] * inv1, o[nt][3] * inv1);
    }
}

// =====================================================================
// LayerNorm over last dim (1024), one CTA (256 thr) per row
// =====================================================================
__global__ __launch_bounds__(256) void layernorm_k(
    const float* __restrict__ X, const float* __restrict__ gamma,
    const float* __restrict__ beta, float* __restrict__ out)
{
    __shared__ float red[16];
    const int row = blockIdx.x;
    const int tid = threadIdx.x;
    const float* x = X + (size_t)row * D_DIM;

    float4 v = *(const float4*)(x + tid * 4);
    float s  = v.x + v.y + v.z + v.w;
    float sq = v.x * v.x + v.y * v.y + v.z * v.z + v.w * v.w;
#pragma unroll
    for (int off = 16; off; off >>= 1) {
        s  += __shfl_xor_sync(0xffffffffu, s, off);
        sq += __shfl_xor_sync(0xffffffffu, sq, off);
    }
    const int wid = tid >> 5;
    if ((tid & 31) == 0) { red[wid] = s; red[8 + wid] = sq; }
    __syncthreads();
    if (tid < 32) {
        float ss = (tid < 8) ? red[tid] : 0.f;
        float qq = (tid < 8) ? red[8 + tid] : 0.f;
#pragma unroll
        for (int off = 4; off; off >>= 1) {
            ss += __shfl_xor_sync(0xffffffffu, ss, off);
            qq += __shfl_xor_sync(0xffffffffu, qq, off);
        }
        if (tid == 0) { red[0] = ss; red[1] = qq; }
    }
    __syncthreads();
    const float mu   = red[0] * (1.f / D_DIM);
    const float var  = red[1] * (1.f / D_DIM) - mu * mu;
    const float rstd = rsqrtf(var + 1e-12f);

    float4 g4 = *(const float4*)(gamma + tid * 4);
    float4 b4 = *(const float4*)(beta + tid * 4);
    float4 r;
    r.x = (v.x - mu) * rstd * g4.x + b4.x;
    r.y = (v.y - mu) * rstd * g4.y + b4.y;
    r.z = (v.z - mu) * rstd * g4.z + b4.z;
    r.w = (v.w - mu) * rstd * g4.w + b4.w;
    *(float4*)(out + (size_t)row * D_DIM + tid * 4) = r;
}

// =====================================================================
// launch
// =====================================================================
extern "C" void kernel_launch(void* const* d_in, const int* in_sizes, int n_in,
                              void* d_out, int out_size)
{
    const float* hs   = (const float*)d_in[0];
    const float* mask = (const float*)d_in[1];
    const float* Wq   = (const float*)d_in[2];
    const float* bq   = (const float*)d_in[3];
    const float* Wk   = (const float*)d_in[4];
    const float* bk   = (const float*)d_in[5];
    const float* Wv   = (const float*)d_in[6];
    const float* bv   = (const float*)d_in[7];
    const float* Wo   = (const float*)d_in[8];
    const float* bo   = (const float*)d_in[9];
    const float* gm   = (const float*)d_in[10];
    const float* bt   = (const float*)d_in[11];
    float* out = (float*)d_out;

    float *qp, *kp, *vp, *cp, *xp;
    cudaGetSymbolAddress((void**)&qp, g_q);
    cudaGetSymbolAddress((void**)&kp, g_k);
    cudaGetSymbolAddress((void**)&vp, g_v);
    cudaGetSymbolAddress((void**)&cp, g_ctx);
    cudaGetSymbolAddress((void**)&xp, g_x);

    cudaFuncSetAttribute(gemm_tf32<0>, cudaFuncAttributeMaxDynamicSharedMemorySize, GEMM_SMEM);
    cudaFuncSetAttribute(gemm_tf32<1>, cudaFuncAttributeMaxDynamicSharedMemorySize, GEMM_SMEM);
    cudaFuncSetAttribute(flash_tf32, cudaFuncAttributeMaxDynamicSharedMemorySize, FL_SMEM);

    // fused QKV projections (blockIdx.z selects W/bias/out)
    gemm_tf32<0><<<dim3(D_DIM / 128, M_ROWS / 128, 3), 256, GEMM_SMEM>>>(
        hs, Wq, Wk, Wv, bq, bk, bv, nullptr, qp, kp, vp);

    flash_tf32<<<dim3(S_LEN / 64, BATCH * N_HEADS), 128, FL_SMEM>>>(qp, kp, vp, mask, cp);

    gemm_tf32<1><<<dim3(D_DIM / 128, M_ROWS / 128, 1), 256, GEMM_SMEM>>>(
        cp, Wo, Wo, Wo, bo, bo, bo, hs, xp, xp, xp);

    layernorm_k<<<M_ROWS, 256>>>(xp, gm, bt, out);
}

// round 5
// speedup vs baseline: 3.4492x; 1.4483x over previous
#include <cuda_runtime.h>
#include <cuda_bf16.h>
#include <cstdint>

// ---------------- problem constants ----------------
#define BATCH    2
#define S_LEN    2048
#define D_DIM    1024
#define N_HEADS  16
#define HEAD_DIM 64
#define M_ROWS   (BATCH * S_LEN)   // 4096

// ---------------- device scratch ----------------
__device__ __nv_bfloat16 g_qb[BATCH * N_HEADS * S_LEN * HEAD_DIM];  // [B,H,S,HD], pre-scaled 1/8
__device__ __nv_bfloat16 g_kb[BATCH * N_HEADS * S_LEN * HEAD_DIM];  // [B,H,S,HD]
__device__ __nv_bfloat16 g_vt[BATCH * N_HEADS * HEAD_DIM * S_LEN];  // [B,H,HD,S]  (V transposed)
__device__ float g_ctx[M_ROWS * D_DIM];                             // [B,S,D]
__device__ float g_x[M_ROWS * D_DIM];                               // proj + residual

// ---------------- ptx helpers ----------------
__device__ __forceinline__ void cp_a16(void* s, const void* g) {
    uint32_t sa = (uint32_t)__cvta_generic_to_shared(s);
    asm volatile("cp.async.cg.shared.global [%0], [%1], 16;\n" :: "r"(sa), "l"(g));
}
__device__ __forceinline__ void cp_commit() {
    asm volatile("cp.async.commit_group;\n" ::: "memory");
}
template <int N> __device__ __forceinline__ void cp_wait() {
    asm volatile("cp.async.wait_group %0;\n" :: "n"(N) : "memory");
}
// pack two floats into bf16x2 (lo in low half, hi in high half)
__device__ __forceinline__ uint32_t pack_bf16x2(float lo, float hi) {
    uint32_t r;
    asm("cvt.rn.bf16x2.f32 %0, %1, %2;\n" : "=r"(r) : "f"(hi), "f"(lo));
    return r;
}
// tf32: D(16x8) += A(16x8) * B(8x8)
__device__ __forceinline__ void mma8(float* c, const uint32_t* a, const uint32_t* b) {
    asm volatile(
        "mma.sync.aligned.m16n8k8.row.col.f32.tf32.tf32.f32 "
        "{%0,%1,%2,%3}, {%4,%5,%6,%7}, {%8,%9}, {%0,%1,%2,%3};\n"
        : "+f"(c[0]), "+f"(c[1]), "+f"(c[2]), "+f"(c[3])
        : "r"(a[0]), "r"(a[1]), "r"(a[2]), "r"(a[3]), "r"(b[0]), "r"(b[1]));
}
// bf16: D(16x8) += A(16x16) * B(16x8)
__device__ __forceinline__ void mma16(float* c, const uint32_t* a, const uint32_t* b) {
    asm volatile(
        "mma.sync.aligned.m16n8k16.row.col.f32.bf16.bf16.f32 "
        "{%0,%1,%2,%3}, {%4,%5,%6,%7}, {%8,%9}, {%0,%1,%2,%3};\n"
        : "+f"(c[0]), "+f"(c[1]), "+f"(c[2]), "+f"(c[3])
        : "r"(a[0]), "r"(a[1]), "r"(a[2]), "r"(a[3]), "r"(b[0]), "r"(b[1]));
}

// =====================================================================
// TF32 GEMM: C = A[M,K] * W[K,N] (+bias)
//   MODE 0 (QKV): z=0 -> Q bf16 [B,H,S,HD] scaled 1/8
//                 z=1 -> K bf16 [B,H,S,HD]
//                 z=2 -> V bf16 [B,H,HD,S]  (transposed)
//   MODE 1 (O):   fp32 +bias +resid, row-major
// 128x128x32 tile, 256 thr (8 warps 2x4), warp 64x32, m16n8k8.
// =====================================================================
#define ASTR 36
#define BSTR 132
#define A_ELE (128 * ASTR)
#define B_ELE (32 * BSTR)
#define STAGE (A_ELE + B_ELE)
#define GEMM_SMEM (2 * STAGE * 4)

template <int MODE>
__global__ __launch_bounds__(256) void gemm_tf32(
    const float* __restrict__ A,
    const float* __restrict__ W0, const float* __restrict__ W1, const float* __restrict__ W2,
    const float* __restrict__ bp0, const float* __restrict__ bp1, const float* __restrict__ bp2,
    const float* __restrict__ resid,
    void* __restrict__ C0, void* __restrict__ C1, void* __restrict__ C2)
{
    extern __shared__ float sm[];
    const int K = D_DIM, N = D_DIM;
    const int z = blockIdx.z;
    const float* W    = (z == 0) ? W0  : (z == 1) ? W1  : W2;
    const float* bias = (z == 0) ? bp0 : (z == 1) ? bp1 : bp2;
    void*        C    = (z == 0) ? C0  : (z == 1) ? C1  : C2;

    const int tid  = threadIdx.x;
    const int lane = tid & 31;
    const int g    = lane >> 2, tig = lane & 3;
    const int wid  = tid >> 5;
    const int wm   = wid >> 2, wn = wid & 3;
    const int bm   = blockIdx.y * 128, bn = blockIdx.x * 128;

    const int arow = tid >> 1, acb = (tid & 1) * 16;
    const int brow = tid >> 3, bcb = (tid & 7) * 16;

    float acc[4][4][4];
#pragma unroll
    for (int i = 0; i < 4; i++)
#pragma unroll
        for (int j = 0; j < 4; j++)
#pragma unroll
            for (int r = 0; r < 4; r++) acc[i][j][r] = 0.f;

    {
        float* As = sm;
        float* Bs = sm + A_ELE;
#pragma unroll
        for (int i = 0; i < 4; i++)
            cp_a16(&As[arow * ASTR + acb + 4 * i], &A[(size_t)(bm + arow) * K + acb + 4 * i]);
#pragma unroll
        for (int i = 0; i < 4; i++)
            cp_a16(&Bs[brow * BSTR + bcb + 4 * i], &W[(size_t)brow * N + bn + bcb + 4 * i]);
        cp_commit();
    }

    const int KT = K / 32;
    for (int kt = 0; kt < KT; kt++) {
        if (kt + 1 < KT) {
            float* As = sm + ((kt + 1) & 1) * STAGE;
            float* Bs = As + A_ELE;
            const int k0 = (kt + 1) * 32;
#pragma unroll
            for (int i = 0; i < 4; i++)
                cp_a16(&As[arow * ASTR + acb + 4 * i], &A[(size_t)(bm + arow) * K + k0 + acb + 4 * i]);
#pragma unroll
            for (int i = 0; i < 4; i++)
                cp_a16(&Bs[brow * BSTR + bcb + 4 * i], &W[(size_t)(k0 + brow) * N + bn + bcb + 4 * i]);
            cp_commit();
            cp_wait<1>();
        } else {
            cp_wait<0>();
        }
        __syncthreads();

        const float* As = sm + (kt & 1) * STAGE;
        const float* Bs = As + A_ELE;
#pragma unroll
        for (int kk = 0; kk < 32; kk += 8) {
            uint32_t af[4][4], bf[4][2];
#pragma unroll
            for (int mt = 0; mt < 4; mt++) {
                const int r0 = wm * 64 + mt * 16;
                af[mt][0] = __float_as_uint(As[(r0 + g) * ASTR + kk + tig]);
                af[mt][1] = __float_as_uint(As[(r0 + g + 8) * ASTR + kk + tig]);
                af[mt][2] = __float_as_uint(As[(r0 + g) * ASTR + kk + tig + 4]);
                af[mt][3] = __float_as_uint(As[(r0 + g + 8) * ASTR + kk + tig + 4]);
            }
#pragma unroll
            for (int nt = 0; nt < 4; nt++) {
                const int c0 = wn * 32 + nt * 8;
                bf[nt][0] = __float_as_uint(Bs[(kk + tig) * BSTR + c0 + g]);
                bf[nt][1] = __float_as_uint(Bs[(kk + tig + 4) * BSTR + c0 + g]);
            }
#pragma unroll
            for (int mt = 0; mt < 4; mt++)
#pragma unroll
                for (int nt = 0; nt < 4; nt++)
                    mma8(acc[mt][nt], af[mt], bf[nt]);
        }
        __syncthreads();
    }

    // epilogue
    const float qscale = (MODE == 0 && z == 0) ? 0.125f : 1.f;
#pragma unroll
    for (int mt = 0; mt < 4; mt++) {
#pragma unroll
        for (int nt = 0; nt < 4; nt++) {
            const int n  = bn + wn * 32 + nt * 8 + 2 * tig;
            const float bx = bias[n], by = bias[n + 1];
#pragma unroll
            for (int half = 0; half < 2; half++) {
                const int m = bm + wm * 64 + mt * 16 + g + half * 8;
                float rx = (acc[mt][nt][half * 2 + 0] + bx) * qscale;
                float ry = (acc[mt][nt][half * 2 + 1] + by) * qscale;
                if (MODE == 0) {
                    const int bb = m >> 11, srow = m & (S_LEN - 1);
                    const int hh = n >> 6, dd = n & 63;
                    __nv_bfloat16* Cb = (__nv_bfloat16*)C;
                    if (z == 2) {
                        // transposed: [B,H,HD,S]
                        size_t idx = ((size_t)(bb * N_HEADS + hh) * HEAD_DIM + dd) * S_LEN + srow;
                        Cb[idx]         = __float2bfloat16(rx);
                        Cb[idx + S_LEN] = __float2bfloat16(ry);
                    } else {
                        size_t idx = (((size_t)bb * N_HEADS + hh) * S_LEN + srow) * HEAD_DIM + dd;
                        uint32_t pk = pack_bf16x2(rx, ry);
                        *(uint32_t*)(Cb + idx) = pk;
                    }
                } else {
                    float* Cf = (float*)C;
                    size_t idx = (size_t)m * D_DIM + n;
                    float2 rr = *(const float2*)(resid + idx);
                    *(float2*)(Cf + idx) = make_float2(rx + rr.x, ry + rr.y);
                }
            }
        }
    }
}

// =====================================================================
// BF16 flash attention: CTA = 64 Q rows of one (b,h), 4 warps (16 rows ea),
// 64-key tiles. K smem [key][72h], V^T smem [d][72h]. m16n8k16 bf16 MMA.
// P stays in registers (C-frag of S == A-frag of PV).
// =====================================================================
#define KSTH 72                                  // halfs per smem row
#define KV_H (64 * KSTH)                         // halfs per tile
#define FL_SMEM (4 * KV_H * 2)                   // K0,K1,V0,V1 = 36864 B

__global__ __launch_bounds__(128) void flash_bf16(
    const __nv_bfloat16* __restrict__ Q, const __nv_bfloat16* __restrict__ K,
    const __nv_bfloat16* __restrict__ Vt, const float* __restrict__ mask,
    float* __restrict__ O)
{
    extern __shared__ __nv_bfloat16 smh[];
    __nv_bfloat16* Kbuf[2] = { smh, smh + KV_H };
    __nv_bfloat16* Vbuf[2] = { smh + 2 * KV_H, smh + 3 * KV_H };

    const int bh = blockIdx.y;
    const int b  = bh >> 4, h = bh & 15;
    const int qb = blockIdx.x;
    const int tid  = threadIdx.x;
    const int wid  = tid >> 5, lane = tid & 31;
    const int g    = lane >> 2, tig = lane & 3;
    const int r0   = wid * 16;

    const __nv_bfloat16* Qp  = Q  + ((size_t)bh * S_LEN + qb * 64) * HEAD_DIM;
    const __nv_bfloat16* Kp  = K  + (size_t)bh * S_LEN * HEAD_DIM;
    const __nv_bfloat16* Vtp = Vt + (size_t)bh * HEAD_DIM * S_LEN;
    const float* mp = mask + (size_t)b * S_LEN;

    // ---- prefetch tile 0 (K rows: [key][d], V^T rows: [d][key]) ----
    {
        __nv_bfloat16* Ks0 = Kbuf[0];
        __nv_bfloat16* Vs0 = Vbuf[0];
#pragma unroll
        for (int i = 0; i < 4; i++) {                 // 512 16B-chunks / 128 thr
            const int idx = i * 128 + tid;
            const int r = idx >> 3, c8 = (idx & 7) * 8;
            cp_a16(&Ks0[r * KSTH + c8], &Kp[(size_t)r * HEAD_DIM + c8]);
        }
#pragma unroll
        for (int i = 0; i < 4; i++) {
            const int idx = i * 128 + tid;
            const int r = idx >> 3, c8 = (idx & 7) * 8;
            cp_a16(&Vs0[r * KSTH + c8], &Vtp[(size_t)r * S_LEN + c8]);
        }
        cp_commit();
    }

    // ---- Q fragments straight from global (bf16, pre-scaled by 1/8) ----
    uint32_t qf[4][4];
#pragma unroll
    for (int kc = 0; kc < 4; kc++) {
        const int kk = kc * 16;
        qf[kc][0] = *(const uint32_t*)&Qp[(size_t)(r0 + g)     * HEAD_DIM + kk + tig * 2];
        qf[kc][1] = *(const uint32_t*)&Qp[(size_t)(r0 + g + 8) * HEAD_DIM + kk + tig * 2];
        qf[kc][2] = *(const uint32_t*)&Qp[(size_t)(r0 + g)     * HEAD_DIM + kk + 8 + tig * 2];
        qf[kc][3] = *(const uint32_t*)&Qp[(size_t)(r0 + g + 8) * HEAD_DIM + kk + 8 + tig * 2];
    }

    float m0 = -1e30f, m1 = -1e30f, l0 = 0.f, l1 = 0.f;
    float o[8][4];
#pragma unroll
    for (int nt = 0; nt < 8; nt++)
#pragma unroll
        for (int r = 0; r < 4; r++) o[nt][r] = 0.f;

    const int NTILE = S_LEN / 64;   // 32
    for (int kb = 0; kb < NTILE; kb++) {
        if (kb + 1 < NTILE) {
            __nv_bfloat16* Ksn = Kbuf[(kb + 1) & 1];
            __nv_bfloat16* Vsn = Vbuf[(kb + 1) & 1];
            const __nv_bfloat16* kp = Kp + (size_t)(kb + 1) * 64 * HEAD_DIM;
            const __nv_bfloat16* vp = Vtp + (size_t)(kb + 1) * 64;
#pragma unroll
            for (int i = 0; i < 4; i++) {
                const int idx = i * 128 + tid;
                const int r = idx >> 3, c8 = (idx & 7) * 8;
                cp_a16(&Ksn[r * KSTH + c8], &kp[(size_t)r * HEAD_DIM + c8]);
            }
#pragma unroll
            for (int i = 0; i < 4; i++) {
                const int idx = i * 128 + tid;
                const int r = idx >> 3, c8 = (idx & 7) * 8;
                cp_a16(&Vsn[r * KSTH + c8], &vp[(size_t)r * S_LEN + c8]);
            }
            cp_commit();
            cp_wait<1>();
        } else {
            cp_wait<0>();
        }
        __syncthreads();

        const __nv_bfloat16* Ks = Kbuf[kb & 1];
        const __nv_bfloat16* Vs = Vbuf[kb & 1];

        // ---- S = Q * K^T (warp: 16 x 64) ----
        float s[8][4];
#pragma unroll
        for (int nt = 0; nt < 8; nt++)
#pragma unroll
            for (int r = 0; r < 4; r++) s[nt][r] = 0.f;

#pragma unroll
        for (int kc = 0; kc < 4; kc++) {
            const int kk = kc * 16;
#pragma unroll
            for (int nt = 0; nt < 8; nt++) {
                uint32_t bf[2];
                bf[0] = *(const uint32_t*)&Ks[(nt * 8 + g) * KSTH + kk + tig * 2];
                bf[1] = *(const uint32_t*)&Ks[(nt * 8 + g) * KSTH + kk + 8 + tig * 2];
                mma16(s[nt], qf[kc], bf);
            }
        }

        // ---- mask + online softmax ----
        const float* mkp = mp + kb * 64;
        float mx0 = -1e30f, mx1 = -1e30f;
#pragma unroll
        for (int nt = 0; nt < 8; nt++) {
            const float ma = mkp[nt * 8 + 2 * tig];
            const float mb = mkp[nt * 8 + 2 * tig + 1];
            s[nt][0] += ma; s[nt][1] += mb; s[nt][2] += ma; s[nt][3] += mb;
            mx0 = fmaxf(mx0, fmaxf(s[nt][0], s[nt][1]));
            mx1 = fmaxf(mx1, fmaxf(s[nt][2], s[nt][3]));
        }
#pragma unroll
        for (int off = 1; off <= 2; off <<= 1) {
            mx0 = fmaxf(mx0, __shfl_xor_sync(0xffffffffu, mx0, off));
            mx1 = fmaxf(mx1, __shfl_xor_sync(0xffffffffu, mx1, off));
        }
        const float mn0 = fmaxf(m0, mx0), mn1 = fmaxf(m1, mx1);
        const float al0 = __expf(m0 - mn0), al1 = __expf(m1 - mn1);
        m0 = mn0; m1 = mn1;

        float rs0 = 0.f, rs1 = 0.f;
#pragma unroll
        for (int nt = 0; nt < 8; nt++) {
            s[nt][0] = __expf(s[nt][0] - mn0);
            s[nt][1] = __expf(s[nt][1] - mn0);
            s[nt][2] = __expf(s[nt][2] - mn1);
            s[nt][3] = __expf(s[nt][3] - mn1);
            rs0 += s[nt][0] + s[nt][1];
            rs1 += s[nt][2] + s[nt][3];
        }
#pragma unroll
        for (int off = 1; off <= 2; off <<= 1) {
            rs0 += __shfl_xor_sync(0xffffffffu, rs0, off);
            rs1 += __shfl_xor_sync(0xffffffffu, rs1, off);
        }
        l0 = l0 * al0 + rs0;
        l1 = l1 * al1 + rs1;

#pragma unroll
        for (int nt = 0; nt < 8; nt++) {
            o[nt][0] *= al0; o[nt][1] *= al0;
            o[nt][2] *= al1; o[nt][3] *= al1;
        }

        // ---- P -> bf16 A-fragments (pure register repack) ----
        uint32_t pf[4][4];
#pragma unroll
        for (int kc = 0; kc < 4; kc++) {
            pf[kc][0] = pack_bf16x2(s[2 * kc][0],     s[2 * kc][1]);
            pf[kc][1] = pack_bf16x2(s[2 * kc][2],     s[2 * kc][3]);
            pf[kc][2] = pack_bf16x2(s[2 * kc + 1][0], s[2 * kc + 1][1]);
            pf[kc][3] = pack_bf16x2(s[2 * kc + 1][2], s[2 * kc + 1][3]);
        }

        // ---- O += P * V (warp: 16 x 64, k = 64 keys) ----
#pragma unroll
        for (int kc = 0; kc < 4; kc++) {
            const int kk = kc * 16;
#pragma unroll
            for (int nt = 0; nt < 8; nt++) {
                uint32_t bf[2];
                bf[0] = *(const uint32_t*)&Vs[(nt * 8 + g) * KSTH + kk + tig * 2];
                bf[1] = *(const uint32_t*)&Vs[(nt * 8 + g) * KSTH + kk + 8 + tig * 2];
                mma16(o[nt], pf[kc], bf);
            }
        }
        __syncthreads();   // protect K/V buffers before next refill
    }

    // ---- write ctx [B,S,D] ----
    const float inv0 = 1.f / l0, inv1 = 1.f / l1;
#pragma unroll
    for (int nt = 0; nt < 8; nt++) {
        const int col = h * HEAD_DIM + nt * 8 + 2 * tig;
        const int row = qb * 64 + r0 + g;
        *(float2*)(O + ((size_t)b * S_LEN + row) * D_DIM + col) =
            make_float2(o[nt][0] * inv0, o[nt][1] * inv0);
        *(float2*)(O + ((size_t)b * S_LEN + row + 8) * D_DIM + col) =
            make_float2(o[nt][2] * inv1, o[nt][3] * inv1);
    }
}

// =====================================================================
// LayerNorm over last dim (1024), one CTA (256 thr) per row
// =====================================================================
__global__ __launch_bounds__(256) void layernorm_k(
    const float* __restrict__ X, const float* __restrict__ gamma,
    const float* __restrict__ beta, float* __restrict__ out)
{
    __shared__ float red[16];
    const int row = blockIdx.x;
    const int tid = threadIdx.x;
    const float* x = X + (size_t)row * D_DIM;

    float4 v = *(const float4*)(x + tid * 4);
    float s  = v.x + v.y + v.z + v.w;
    float sq = v.x * v.x + v.y * v.y + v.z * v.z + v.w * v.w;
#pragma unroll
    for (int off = 16; off; off >>= 1) {
        s  += __shfl_xor_sync(0xffffffffu, s, off);
        sq += __shfl_xor_sync(0xffffffffu, sq, off);
    }
    const int wid = tid >> 5;
    if ((tid & 31) == 0) { red[wid] = s; red[8 + wid] = sq; }
    __syncthreads();
    if (tid < 32) {
        float ss = (tid < 8) ? red[tid] : 0.f;
        float qq = (tid < 8) ? red[8 + tid] : 0.f;
#pragma unroll
        for (int off = 4; off; off >>= 1) {
            ss += __shfl_xor_sync(0xffffffffu, ss, off);
            qq += __shfl_xor_sync(0xffffffffu, qq, off);
        }
        if (tid == 0) { red[0] = ss; red[1] = qq; }
    }
    __syncthreads();
    const float mu   = red[0] * (1.f / D_DIM);
    const float var  = red[1] * (1.f / D_DIM) - mu * mu;
    const float rstd = rsqrtf(var + 1e-12f);

    float4 g4 = *(const float4*)(gamma + tid * 4);
    float4 b4 = *(const float4*)(beta + tid * 4);
    float4 r;
    r.x = (v.x - mu) * rstd * g4.x + b4.x;
    r.y = (v.y - mu) * rstd * g4.y + b4.y;
    r.z = (v.z - mu) * rstd * g4.z + b4.z;
    r.w = (v.w - mu) * rstd * g4.w + b4.w;
    *(float4*)(out + (size_t)row * D_DIM + tid * 4) = r;
}

// =====================================================================
// launch
// =====================================================================
extern "C" void kernel_launch(void* const* d_in, const int* in_sizes, int n_in,
                              void* d_out, int out_size)
{
    const float* hs   = (const float*)d_in[0];
    const float* mask = (const float*)d_in[1];
    const float* Wq   = (const float*)d_in[2];
    const float* bq   = (const float*)d_in[3];
    const float* Wk   = (const float*)d_in[4];
    const float* bk   = (const float*)d_in[5];
    const float* Wv   = (const float*)d_in[6];
    const float* bv   = (const float*)d_in[7];
    const float* Wo   = (const float*)d_in[8];
    const float* bo   = (const float*)d_in[9];
    const float* gm   = (const float*)d_in[10];
    const float* bt   = (const float*)d_in[11];
    float* out = (float*)d_out;

    void *qp, *kp, *vp;
    float *cp, *xp;
    cudaGetSymbolAddress(&qp, g_qb);
    cudaGetSymbolAddress(&kp, g_kb);
    cudaGetSymbolAddress(&vp, g_vt);
    cudaGetSymbolAddress((void**)&cp, g_ctx);
    cudaGetSymbolAddress((void**)&xp, g_x);

    cudaFuncSetAttribute(gemm_tf32<0>, cudaFuncAttributeMaxDynamicSharedMemorySize, GEMM_SMEM);
    cudaFuncSetAttribute(gemm_tf32<1>, cudaFuncAttributeMaxDynamicSharedMemorySize, GEMM_SMEM);
    cudaFuncSetAttribute(flash_bf16, cudaFuncAttributeMaxDynamicSharedMemorySize, FL_SMEM);

    // fused QKV projections -> bf16 Q (scaled), bf16 K, bf16 V^T
    gemm_tf32<0><<<dim3(D_DIM / 128, M_ROWS / 128, 3), 256, GEMM_SMEM>>>(
        hs, Wq, Wk, Wv, bq, bk, bv, nullptr, qp, kp, vp);

    flash_bf16<<<dim3(S_LEN / 64, BATCH * N_HEADS), 128, FL_SMEM>>>(
        (const __nv_bfloat16*)qp, (const __nv_bfloat16*)kp,
        (const __nv_bfloat16*)vp, mask, cp);

    gemm_tf32<1><<<dim3(D_DIM / 128, M_ROWS / 128, 1), 256, GEMM_SMEM>>>(
        cp, Wo, Wo, Wo, bo, bo, bo, hs, xp, xp, xp);

    layernorm_k<<<M_ROWS, 256>>>(xp, gm, bt, out);
}

// round 6
// speedup vs baseline: 5.6995x; 1.6524x over previous
#include <cuda_runtime.h>
#include <cuda_bf16.h>
#include <cstdint>

// ---------------- problem constants ----------------
#define BATCH    2
#define S_LEN    2048
#define D_DIM    1024
#define N_HEADS  16
#define HEAD_DIM 64
#define M_ROWS   (BATCH * S_LEN)   // 4096

// ---------------- device scratch ----------------
__device__ __nv_bfloat16 g_hsb[M_ROWS * D_DIM];                     // hidden bf16
__device__ __nv_bfloat16 g_wt[4][D_DIM * D_DIM];                    // W^T bf16 [N][K] (q,k,v,o)
__device__ __nv_bfloat16 g_qb[BATCH * N_HEADS * S_LEN * HEAD_DIM];  // [B,H,S,HD], pre-scaled 1/8
__device__ __nv_bfloat16 g_kb[BATCH * N_HEADS * S_LEN * HEAD_DIM];  // [B,H,S,HD]
__device__ __nv_bfloat16 g_vt[BATCH * N_HEADS * HEAD_DIM * S_LEN];  // [B,H,HD,S]  (V transposed)
__device__ __nv_bfloat16 g_ctx[M_ROWS * D_DIM];                     // [B,S,D] bf16
__device__ float g_x[M_ROWS * D_DIM];                               // proj + residual

// ---------------- ptx helpers ----------------
__device__ __forceinline__ void cp_a16(void* s, const void* g) {
    uint32_t sa = (uint32_t)__cvta_generic_to_shared(s);
    asm volatile("cp.async.cg.shared.global [%0], [%1], 16;\n" :: "r"(sa), "l"(g));
}
__device__ __forceinline__ void cp_commit() {
    asm volatile("cp.async.commit_group;\n" ::: "memory");
}
template <int N> __device__ __forceinline__ void cp_wait() {
    asm volatile("cp.async.wait_group %0;\n" :: "n"(N) : "memory");
}
// pack two floats into bf16x2 (lo in low half, hi in high half)
__device__ __forceinline__ uint32_t pack_bf16x2(float lo, float hi) {
    uint32_t r;
    asm("cvt.rn.bf16x2.f32 %0, %1, %2;\n" : "=r"(r) : "f"(hi), "f"(lo));
    return r;
}
// bf16: D(16x8) += A(16x16) * B(16x8)
__device__ __forceinline__ void mma16(float* c, const uint32_t* a, const uint32_t* b) {
    asm volatile(
        "mma.sync.aligned.m16n8k16.row.col.f32.bf16.bf16.f32 "
        "{%0,%1,%2,%3}, {%4,%5,%6,%7}, {%8,%9}, {%0,%1,%2,%3};\n"
        : "+f"(c[0]), "+f"(c[1]), "+f"(c[2]), "+f"(c[3])
        : "r"(a[0]), "r"(a[1]), "r"(a[2]), "r"(a[3]), "r"(b[0]), "r"(b[1]));
}

// =====================================================================
// Prep kernels: fp32 -> bf16 convert (hs) and transpose+convert (W -> W^T)
// =====================================================================
__global__ __launch_bounds__(256) void conv_hs(const float* __restrict__ X,
                                               __nv_bfloat16* __restrict__ Y)
{
    const int i = (blockIdx.x * 256 + threadIdx.x) * 4;
    float4 v = *(const float4*)(X + i);
    uint32_t p0 = pack_bf16x2(v.x, v.y);
    uint32_t p1 = pack_bf16x2(v.z, v.w);
    *(uint2*)(Y + i) = make_uint2(p0, p1);
}

// 32x32 tiled transpose: W[K][N] fp32 -> Wt[N][K] bf16, blockIdx.z selects matrix
__global__ __launch_bounds__(256) void conv_wt(
    const float* __restrict__ W0, const float* __restrict__ W1,
    const float* __restrict__ W2, const float* __restrict__ W3,
    __nv_bfloat16* __restrict__ Wt)
{
    __shared__ float t[32][33];
    const int z = blockIdx.z;
    const float* W = (z == 0) ? W0 : (z == 1) ? W1 : (z == 2) ? W2 : W3;
    __nv_bfloat16* T = Wt + (size_t)z * D_DIM * D_DIM;

    const int tx = threadIdx.x & 31, ty = threadIdx.x >> 5;   // 32 x 8
    const int k0 = blockIdx.y * 32, n0 = blockIdx.x * 32;
#pragma unroll
    for (int i = 0; i < 4; i++)
        t[ty + i * 8][tx] = W[(size_t)(k0 + ty + i * 8) * D_DIM + n0 + tx];
    __syncthreads();
#pragma unroll
    for (int i = 0; i < 4; i++) {
        const int n = n0 + ty + i * 8;
        T[(size_t)n * D_DIM + k0 + tx] = __float2bfloat16(t[tx][ty + i * 8]);
    }
}

// =====================================================================
// BF16 GEMM: C = A[M,K](bf16) * Wt[N,K](bf16)^T (+bias)
//   MODE 0 (QKV): z=0 -> Q bf16 [B,H,S,HD] scaled 1/8
//                 z=1 -> K bf16 [B,H,S,HD]
//                 z=2 -> V bf16 [B,H,HD,S]  (transposed)
//   MODE 1 (O):   fp32 +bias +resid, row-major
// 128x128x64 tile, 256 thr (8 warps 2x4), warp 64x32, m16n8k16.
// Both smem tiles [128 rows][72 halfs] (144B stride, conflict-free frags).
// =====================================================================
#define HSTR 72
#define TILE_H (128 * HSTR)               // halfs per operand stage
#define STAGE_H (2 * TILE_H)
#define GEMM_SMEM (2 * STAGE_H * 2)       // 2 stages * (A+B) * 2B = 73728

template <int MODE>
__global__ __launch_bounds__(256) void gemm_bf16(
    const __nv_bfloat16* __restrict__ A, const __nv_bfloat16* __restrict__ Wt,
    const float* __restrict__ bp0, const float* __restrict__ bp1, const float* __restrict__ bp2,
    const float* __restrict__ resid,
    void* __restrict__ C0, void* __restrict__ C1, void* __restrict__ C2)
{
    extern __shared__ __nv_bfloat16 smh[];
    const int K = D_DIM;
    const int z = blockIdx.z;
    const __nv_bfloat16* Wz = Wt + (size_t)z * D_DIM * D_DIM;
    const float* bias = (z == 0) ? bp0 : (z == 1) ? bp1 : bp2;
    void*        C    = (z == 0) ? C0  : (z == 1) ? C1  : C2;

    const int tid  = threadIdx.x;
    const int lane = tid & 31;
    const int g    = lane >> 2, tig = lane & 3;
    const int wid  = tid >> 5;
    const int wm   = wid >> 2, wn = wid & 3;
    const int bm   = blockIdx.y * 128, bn = blockIdx.x * 128;

    float acc[4][4][4];
#pragma unroll
    for (int i = 0; i < 4; i++)
#pragma unroll
        for (int j = 0; j < 4; j++)
#pragma unroll
            for (int r = 0; r < 4; r++) acc[i][j][r] = 0.f;

    // stage loaders: 128 rows x 64 halfs = 1024 x 16B chunks per operand
    auto load_stage = [&](int st, int k0) {
        __nv_bfloat16* As = smh + st * STAGE_H;
        __nv_bfloat16* Bs = As + TILE_H;
#pragma unroll
        for (int i = 0; i < 4; i++) {
            const int idx = i * 256 + tid;
            const int r = idx >> 3, c8 = (idx & 7) * 8;
            cp_a16(&As[r * HSTR + c8], &A[(size_t)(bm + r) * K + k0 + c8]);
        }
#pragma unroll
        for (int i = 0; i < 4; i++) {
            const int idx = i * 256 + tid;
            const int r = idx >> 3, c8 = (idx & 7) * 8;
            cp_a16(&Bs[r * HSTR + c8], &Wz[(size_t)(bn + r) * K + k0 + c8]);
        }
        cp_commit();
    };

    load_stage(0, 0);

    const int KT = K / 64;   // 16
    for (int kt = 0; kt < KT; kt++) {
        if (kt + 1 < KT) {
            load_stage((kt + 1) & 1, (kt + 1) * 64);
            cp_wait<1>();
        } else {
            cp_wait<0>();
        }
        __syncthreads();

        const __nv_bfloat16* As = smh + (kt & 1) * STAGE_H;
        const __nv_bfloat16* Bs = As + TILE_H;
#pragma unroll
        for (int kk = 0; kk < 64; kk += 16) {
            uint32_t af[4][4], bf[4][2];
#pragma unroll
            for (int mt = 0; mt < 4; mt++) {
                const int r0 = wm * 64 + mt * 16;
                af[mt][0] = *(const uint32_t*)&As[(r0 + g)     * HSTR + kk + tig * 2];
                af[mt][1] = *(const uint32_t*)&As[(r0 + g + 8) * HSTR + kk + tig * 2];
                af[mt][2] = *(const uint32_t*)&As[(r0 + g)     * HSTR + kk + 8 + tig * 2];
                af[mt][3] = *(const uint32_t*)&As[(r0 + g + 8) * HSTR + kk + 8 + tig * 2];
            }
#pragma unroll
            for (int nt = 0; nt < 4; nt++) {
                const int c0 = wn * 32 + nt * 8;
                bf[nt][0] = *(const uint32_t*)&Bs[(c0 + g) * HSTR + kk + tig * 2];
                bf[nt][1] = *(const uint32_t*)&Bs[(c0 + g) * HSTR + kk + 8 + tig * 2];
            }
#pragma unroll
            for (int mt = 0; mt < 4; mt++)
#pragma unroll
                for (int nt = 0; nt < 4; nt++)
                    mma16(acc[mt][nt], af[mt], bf[nt]);
        }
        __syncthreads();
    }

    // epilogue
    const float qscale = (MODE == 0 && z == 0) ? 0.125f : 1.f;
#pragma unroll
    for (int mt = 0; mt < 4; mt++) {
#pragma unroll
        for (int nt = 0; nt < 4; nt++) {
            const int n  = bn + wn * 32 + nt * 8 + 2 * tig;
            const float bx = bias[n], by = bias[n + 1];
#pragma unroll
            for (int half = 0; half < 2; half++) {
                const int m = bm + wm * 64 + mt * 16 + g + half * 8;
                float rx = (acc[mt][nt][half * 2 + 0] + bx) * qscale;
                float ry = (acc[mt][nt][half * 2 + 1] + by) * qscale;
                if (MODE == 0) {
                    const int bb = m >> 11, srow = m & (S_LEN - 1);
                    const int hh = n >> 6, dd = n & 63;
                    __nv_bfloat16* Cb = (__nv_bfloat16*)C;
                    if (z == 2) {
                        // V transposed: [B,H,HD,S]
                        size_t idx = ((size_t)(bb * N_HEADS + hh) * HEAD_DIM + dd) * S_LEN + srow;
                        Cb[idx]         = __float2bfloat16(rx);
                        Cb[idx + S_LEN] = __float2bfloat16(ry);
                    } else {
                        size_t idx = (((size_t)bb * N_HEADS + hh) * S_LEN + srow) * HEAD_DIM + dd;
                        *(uint32_t*)(Cb + idx) = pack_bf16x2(rx, ry);
                    }
                } else {
                    float* Cf = (float*)C;
                    size_t idx = (size_t)m * D_DIM + n;
                    float2 rr = *(const float2*)(resid + idx);
                    *(float2*)(Cf + idx) = make_float2(rx + rr.x, ry + rr.y);
                }
            }
        }
    }
}

// =====================================================================
// BF16 flash attention: CTA = 64 Q rows of one (b,h), 4 warps (16 rows ea),
// 64-key tiles. K smem [key][72h], V^T smem [d][72h]. m16n8k16 bf16 MMA.
// P stays in registers (C-frag of S == A-frag of PV). ctx written bf16.
// =====================================================================
#define KSTH 72
#define KV_H (64 * KSTH)
#define FL_SMEM (4 * KV_H * 2)   // K0,K1,V0,V1 = 36864 B

__global__ __launch_bounds__(128) void flash_bf16(
    const __nv_bfloat16* __restrict__ Q, const __nv_bfloat16* __restrict__ K,
    const __nv_bfloat16* __restrict__ Vt, const float* __restrict__ mask,
    __nv_bfloat16* __restrict__ O)
{
    extern __shared__ __nv_bfloat16 smh[];
    __nv_bfloat16* Kbuf[2] = { smh, smh + KV_H };
    __nv_bfloat16* Vbuf[2] = { smh + 2 * KV_H, smh + 3 * KV_H };

    const int bh = blockIdx.y;
    const int b  = bh >> 4, h = bh & 15;
    const int qb = blockIdx.x;
    const int tid  = threadIdx.x;
    const int wid  = tid >> 5, lane = tid & 31;
    const int g    = lane >> 2, tig = lane & 3;
    const int r0   = wid * 16;

    const __nv_bfloat16* Qp  = Q  + ((size_t)bh * S_LEN + qb * 64) * HEAD_DIM;
    const __nv_bfloat16* Kp  = K  + (size_t)bh * S_LEN * HEAD_DIM;
    const __nv_bfloat16* Vtp = Vt + (size_t)bh * HEAD_DIM * S_LEN;
    const float* mp = mask + (size_t)b * S_LEN;

    // ---- prefetch tile 0 ----
    {
        __nv_bfloat16* Ks0 = Kbuf[0];
        __nv_bfloat16* Vs0 = Vbuf[0];
#pragma unroll
        for (int i = 0; i < 4; i++) {
            const int idx = i * 128 + tid;
            const int r = idx >> 3, c8 = (idx & 7) * 8;
            cp_a16(&Ks0[r * KSTH + c8], &Kp[(size_t)r * HEAD_DIM + c8]);
        }
#pragma unroll
        for (int i = 0; i < 4; i++) {
            const int idx = i * 128 + tid;
            const int r = idx >> 3, c8 = (idx & 7) * 8;
            cp_a16(&Vs0[r * KSTH + c8], &Vtp[(size_t)r * S_LEN + c8]);
        }
        cp_commit();
    }

    // ---- Q fragments from global (bf16, pre-scaled 1/8) ----
    uint32_t qf[4][4];
#pragma unroll
    for (int kc = 0; kc < 4; kc++) {
        const int kk = kc * 16;
        qf[kc][0] = *(const uint32_t*)&Qp[(size_t)(r0 + g)     * HEAD_DIM + kk + tig * 2];
        qf[kc][1] = *(const uint32_t*)&Qp[(size_t)(r0 + g + 8) * HEAD_DIM + kk + tig * 2];
        qf[kc][2] = *(const uint32_t*)&Qp[(size_t)(r0 + g)     * HEAD_DIM + kk + 8 + tig * 2];
        qf[kc][3] = *(const uint32_t*)&Qp[(size_t)(r0 + g + 8) * HEAD_DIM + kk + 8 + tig * 2];
    }

    float m0 = -1e30f, m1 = -1e30f, l0 = 0.f, l1 = 0.f;
    float o[8][4];
#pragma unroll
    for (int nt = 0; nt < 8; nt++)
#pragma unroll
        for (int r = 0; r < 4; r++) o[nt][r] = 0.f;

    const int NTILE = S_LEN / 64;
    for (int kb = 0; kb < NTILE; kb++) {
        if (kb + 1 < NTILE) {
            __nv_bfloat16* Ksn = Kbuf[(kb + 1) & 1];
            __nv_bfloat16* Vsn = Vbuf[(kb + 1) & 1];
            const __nv_bfloat16* kp = Kp + (size_t)(kb + 1) * 64 * HEAD_DIM;
            const __nv_bfloat16* vp = Vtp + (size_t)(kb + 1) * 64;
#pragma unroll
            for (int i = 0; i < 4; i++) {
                const int idx = i * 128 + tid;
                const int r = idx >> 3, c8 = (idx & 7) * 8;
                cp_a16(&Ksn[r * KSTH + c8], &kp[(size_t)r * HEAD_DIM + c8]);
            }
#pragma unroll
            for (int i = 0; i < 4; i++) {
                const int idx = i * 128 + tid;
                const int r = idx >> 3, c8 = (idx & 7) * 8;
                cp_a16(&Vsn[r * KSTH + c8], &vp[(size_t)r * S_LEN + c8]);
            }
            cp_commit();
            cp_wait<1>();
        } else {
            cp_wait<0>();
        }
        __syncthreads();

        const __nv_bfloat16* Ks = Kbuf[kb & 1];
        const __nv_bfloat16* Vs = Vbuf[kb & 1];

        // ---- S = Q * K^T ----
        float s[8][4];
#pragma unroll
        for (int nt = 0; nt < 8; nt++)
#pragma unroll
            for (int r = 0; r < 4; r++) s[nt][r] = 0.f;

#pragma unroll
        for (int kc = 0; kc < 4; kc++) {
            const int kk = kc * 16;
#pragma unroll
            for (int nt = 0; nt < 8; nt++) {
                uint32_t bf[2];
                bf[0] = *(const uint32_t*)&Ks[(nt * 8 + g) * KSTH + kk + tig * 2];
                bf[1] = *(const uint32_t*)&Ks[(nt * 8 + g) * KSTH + kk + 8 + tig * 2];
                mma16(s[nt], qf[kc], bf);
            }
        }

        // ---- mask + online softmax ----
        const float* mkp = mp + kb * 64;
        float mx0 = -1e30f, mx1 = -1e30f;
#pragma unroll
        for (int nt = 0; nt < 8; nt++) {
            const float ma = mkp[nt * 8 + 2 * tig];
            const float mb = mkp[nt * 8 + 2 * tig + 1];
            s[nt][0] += ma; s[nt][1] += mb; s[nt][2] += ma; s[nt][3] += mb;
            mx0 = fmaxf(mx0, fmaxf(s[nt][0], s[nt][1]));
            mx1 = fmaxf(mx1, fmaxf(s[nt][2], s[nt][3]));
        }
#pragma unroll
        for (int off = 1; off <= 2; off <<= 1) {
            mx0 = fmaxf(mx0, __shfl_xor_sync(0xffffffffu, mx0, off));
            mx1 = fmaxf(mx1, __shfl_xor_sync(0xffffffffu, mx1, off));
        }
        const float mn0 = fmaxf(m0, mx0), mn1 = fmaxf(m1, mx1);
        const float al0 = __expf(m0 - mn0), al1 = __expf(m1 - mn1);
        m0 = mn0; m1 = mn1;

        float rs0 = 0.f, rs1 = 0.f;
#pragma unroll
        for (int nt = 0; nt < 8; nt++) {
            s[nt][0] = __expf(s[nt][0] - mn0);
            s[nt][1] = __expf(s[nt][1] - mn0);
            s[nt][2] = __expf(s[nt][2] - mn1);
            s[nt][3] = __expf(s[nt][3] - mn1);
            rs0 += s[nt][0] + s[nt][1];
            rs1 += s[nt][2] + s[nt][3];
        }
#pragma unroll
        for (int off = 1; off <= 2; off <<= 1) {
            rs0 += __shfl_xor_sync(0xffffffffu, rs0, off);
            rs1 += __shfl_xor_sync(0xffffffffu, rs1, off);
        }
        l0 = l0 * al0 + rs0;
        l1 = l1 * al1 + rs1;

#pragma unroll
        for (int nt = 0; nt < 8; nt++) {
            o[nt][0] *= al0; o[nt][1] *= al0;
            o[nt][2] *= al1; o[nt][3] *= al1;
        }

        // ---- P -> bf16 A-fragments ----
        uint32_t pf[4][4];
#pragma unroll
        for (int kc = 0; kc < 4; kc++) {
            pf[kc][0] = pack_bf16x2(s[2 * kc][0],     s[2 * kc][1]);
            pf[kc][1] = pack_bf16x2(s[2 * kc][2],     s[2 * kc][3]);
            pf[kc][2] = pack_bf16x2(s[2 * kc + 1][0], s[2 * kc + 1][1]);
            pf[kc][3] = pack_bf16x2(s[2 * kc + 1][2], s[2 * kc + 1][3]);
        }

        // ---- O += P * V ----
#pragma unroll
        for (int kc = 0; kc < 4; kc++) {
            const int kk = kc * 16;
#pragma unroll
            for (int nt = 0; nt < 8; nt++) {
                uint32_t bf[2];
                bf[0] = *(const uint32_t*)&Vs[(nt * 8 + g) * KSTH + kk + tig * 2];
                bf[1] = *(const uint32_t*)&Vs[(nt * 8 + g) * KSTH + kk + 8 + tig * 2];
                mma16(o[nt], pf[kc], bf);
            }
        }
        __syncthreads();
    }

    // ---- write ctx [B,S,D] bf16 ----
    const float inv0 = 1.f / l0, inv1 = 1.f / l1;
#pragma unroll
    for (int nt = 0; nt < 8; nt++) {
        const int col = h * HEAD_DIM + nt * 8 + 2 * tig;
        const int row = qb * 64 + r0 + g;
        *(uint32_t*)(O + ((size_t)b * S_LEN + row) * D_DIM + col) =
            pack_bf16x2(o[nt][0] * inv0, o[nt][1] * inv0);
        *(uint32_t*)(O + ((size_t)b * S_LEN + row + 8) * D_DIM + col) =
            pack_bf16x2(o[nt][2] * inv1, o[nt][3] * inv1);
    }
}

// =====================================================================
// LayerNorm over last dim (1024), one CTA (256 thr) per row
// =====================================================================
__global__ __launch_bounds__(256) void layernorm_k(
    const float* __restrict__ X, const float* __restrict__ gamma,
    const float* __restrict__ beta, float* __restrict__ out)
{
    __shared__ float red[16];
    const int row = blockIdx.x;
    const int tid = threadIdx.x;
    const float* x = X + (size_t)row * D_DIM;

    float4 v = *(const float4*)(x + tid * 4);
    float s  = v.x + v.y + v.z + v.w;
    float sq = v.x * v.x + v.y * v.y + v.z * v.z + v.w * v.w;
#pragma unroll
    for (int off = 16; off; off >>= 1) {
        s  += __shfl_xor_sync(0xffffffffu, s, off);
        sq += __shfl_xor_sync(0xffffffffu, sq, off);
    }
    const int wid = tid >> 5;
    if ((tid & 31) == 0) { red[wid] = s; red[8 + wid] = sq; }
    __syncthreads();
    if (tid < 32) {
        float ss = (tid < 8) ? red[tid] : 0.f;
        float qq = (tid < 8) ? red[8 + tid] : 0.f;
#pragma unroll
        for (int off = 4; off; off >>= 1) {
            ss += __shfl_xor_sync(0xffffffffu, ss, off);
            qq += __shfl_xor_sync(0xffffffffu, qq, off);
        }
        if (tid == 0) { red[0] = ss; red[1] = qq; }
    }
    __syncthreads();
    const float mu   = red[0] * (1.f / D_DIM);
    const float var  = red[1] * (1.f / D_DIM) - mu * mu;
    const float rstd = rsqrtf(var + 1e-12f);

    float4 g4 = *(const float4*)(gamma + tid * 4);
    float4 b4 = *(const float4*)(beta + tid * 4);
    float4 r;
    r.x = (v.x - mu) * rstd * g4.x + b4.x;
    r.y = (v.y - mu) * rstd * g4.y + b4.y;
    r.z = (v.z - mu) * rstd * g4.z + b4.z;
    r.w = (v.w - mu) * rstd * g4.w + b4.w;
    *(float4*)(out + (size_t)row * D_DIM + tid * 4) = r;
}

// =====================================================================
// launch
// =====================================================================
extern "C" void kernel_launch(void* const* d_in, const int* in_sizes, int n_in,
                              void* d_out, int out_size)
{
    const float* hs   = (const float*)d_in[0];
    const float* mask = (const float*)d_in[1];
    const float* Wq   = (const float*)d_in[2];
    const float* bq   = (const float*)d_in[3];
    const float* Wk   = (const float*)d_in[4];
    const float* bk   = (const float*)d_in[5];
    const float* Wv   = (const float*)d_in[6];
    const float* bv   = (const float*)d_in[7];
    const float* Wo   = (const float*)d_in[8];
    const float* bo   = (const float*)d_in[9];
    const float* gm   = (const float*)d_in[10];
    const float* bt   = (const float*)d_in[11];
    float* out = (float*)d_out;

    void *hsb, *wt, *qp, *kp, *vp, *cp;
    float *xp;
    cudaGetSymbolAddress(&hsb, g_hsb);
    cudaGetSymbolAddress(&wt, g_wt);
    cudaGetSymbolAddress(&qp, g_qb);
    cudaGetSymbolAddress(&kp, g_kb);
    cudaGetSymbolAddress(&vp, g_vt);
    cudaGetSymbolAddress(&cp, g_ctx);
    cudaGetSymbolAddress((void**)&xp, g_x);

    cudaFuncSetAttribute(gemm_bf16<0>, cudaFuncAttributeMaxDynamicSharedMemorySize, GEMM_SMEM);
    cudaFuncSetAttribute(gemm_bf16<1>, cudaFuncAttributeMaxDynamicSharedMemorySize, GEMM_SMEM);
    cudaFuncSetAttribute(flash_bf16, cudaFuncAttributeMaxDynamicSharedMemorySize, FL_SMEM);

    // prep: hs -> bf16, W -> W^T bf16
    conv_hs<<<M_ROWS * D_DIM / 1024, 256>>>(hs, (__nv_bfloat16*)hsb);
    conv_wt<<<dim3(D_DIM / 32, D_DIM / 32, 4), 256>>>(Wq, Wk, Wv, Wo, (__nv_bfloat16*)wt);

    // fused QKV projections -> bf16 Q (scaled), bf16 K, bf16 V^T
    gemm_bf16<0><<<dim3(D_DIM / 128, M_ROWS / 128, 3), 256, GEMM_SMEM>>>(
        (const __nv_bfloat16*)hsb, (const __nv_bfloat16*)wt,
        bq, bk, bv, nullptr, qp, kp, vp);

    flash_bf16<<<dim3(S_LEN / 64, BATCH * N_HEADS), 128, FL_SMEM>>>(
        (const __nv_bfloat16*)qp, (const __nv_bfloat16*)kp,
        (const __nv_bfloat16*)vp, mask, (__nv_bfloat16*)cp);

    // O projection: ctx(bf16) x Wo^T + bo + hs(residual), fp32 out
    gemm_bf16<1><<<dim3(D_DIM / 128, M_ROWS / 128, 1), 256, GEMM_SMEM>>>(
        (const __nv_bfloat16*)cp, (const __nv_bfloat16*)wt + 3 * (size_t)D_DIM * D_DIM,
        bo, bo, bo, hs, xp, xp, xp);

    layernorm_k<<<M_ROWS, 256>>>(xp, gm, bt, out);
}